// round 1
// baseline (speedup 1.0000x reference)
#include <cuda_runtime.h>
#include <cuda_bf16.h>
#include <cstdint>

// ---------------- problem constants ----------------
#define MAXN 20000
#define MAXC 1024
#define NGRAPH 256
#define EPS 1e-5f

// ---------------- scratch (static device memory; no allocs) ----------------
__device__ float g_bufA[(size_t)MAXN * MAXC];  // h
__device__ float g_bufB[(size_t)MAXN * MAXC];  // t
__device__ float g_bufC[(size_t)MAXN * MAXC];  // u
__device__ float g_xw  [(size_t)MAXN * MAXC];
__device__ float g_agg [(size_t)MAXN * MAXC];
__device__ float g_deg [MAXN];
__device__ float g_dinv[MAXN];
__device__ float g_sum [MAXC];
__device__ float g_sumsq[MAXC];
__device__ float g_pool[NGRAPH * MAXC];
__device__ float g_cnt [NGRAPH];
__device__ float g_mlp [NGRAPH * MAXC];

// ---------------- degree / dinv ----------------
__global__ void deg_init_k(float* deg, int n) {
    int i = blockIdx.x * blockDim.x + threadIdx.x;
    if (i < n) deg[i] = 1.0f;
}
__global__ void deg_acc_k(const int* __restrict__ dst, float* deg, int E) {
    int i = blockIdx.x * blockDim.x + threadIdx.x;
    if (i < E) atomicAdd(&deg[dst[i]], 1.0f);
}
__global__ void dinv_k(const float* __restrict__ deg, float* dinv, int n) {
    int i = blockIdx.x * blockDim.x + threadIdx.x;
    if (i < n) dinv[i] = rsqrtf(deg[i]);
}

// ---------------- fp32 tiled GEMM: C[M,N] = A[M,K] @ B[K,N] (+bias)(+relu) ----
// BM=BN=64, BK=16, 256 threads, 4x4 micro-tile.
#define BM 64
#define BN 64
#define BK 16
template<int RELU, int BIAS>
__global__ void gemm_k(const float* __restrict__ A, const float* __restrict__ B,
                       const float* __restrict__ bias, float* __restrict__ C,
                       int M, int K, int N) {
    __shared__ float As[BK][BM];
    __shared__ float Bs[BK][BN];
    const int tid = threadIdx.x;
    const int bcol = blockIdx.x, brow = blockIdx.y;
    const int tx = tid & 15, ty = tid >> 4;

    const int arow  = tid >> 2;          // 0..63
    const int acol4 = (tid & 3) * 4;     // 0,4,8,12
    const int brow_l = tid >> 4;         // 0..15
    const int bcol4  = (tid & 15) * 4;   // 0..60
    const int grow = brow * BM + arow;

    float acc[4][4];
#pragma unroll
    for (int i = 0; i < 4; i++)
#pragma unroll
        for (int j = 0; j < 4; j++) acc[i][j] = 0.f;

    for (int k0 = 0; k0 < K; k0 += BK) {
        float4 av = make_float4(0.f, 0.f, 0.f, 0.f);
        if (grow < M)
            av = *(const float4*)(A + (size_t)grow * K + k0 + acol4);
        As[acol4 + 0][arow] = av.x;
        As[acol4 + 1][arow] = av.y;
        As[acol4 + 2][arow] = av.z;
        As[acol4 + 3][arow] = av.w;
        float4 bv = *(const float4*)(B + (size_t)(k0 + brow_l) * N + bcol * BN + bcol4);
        *(float4*)(&Bs[brow_l][bcol4]) = bv;
        __syncthreads();
#pragma unroll
        for (int k = 0; k < BK; k++) {
            float4 a = *(const float4*)(&As[k][ty * 4]);
            float4 b = *(const float4*)(&Bs[k][tx * 4]);
            float ar[4] = {a.x, a.y, a.z, a.w};
            float br[4] = {b.x, b.y, b.z, b.w};
#pragma unroll
            for (int i = 0; i < 4; i++)
#pragma unroll
                for (int j = 0; j < 4; j++)
                    acc[i][j] += ar[i] * br[j];
        }
        __syncthreads();
    }

    const int row0 = brow * BM + ty * 4;
    const int col0 = bcol * BN + tx * 4;
    float4 bb = make_float4(0.f, 0.f, 0.f, 0.f);
    if (BIAS) bb = *(const float4*)(bias + col0);
#pragma unroll
    for (int i = 0; i < 4; i++) {
        int r = row0 + i;
        if (r < M) {
            float4 v;
            v.x = acc[i][0]; v.y = acc[i][1]; v.z = acc[i][2]; v.w = acc[i][3];
            if (BIAS) { v.x += bb.x; v.y += bb.y; v.z += bb.z; v.w += bb.w; }
            if (RELU) {
                v.x = fmaxf(v.x, 0.f); v.y = fmaxf(v.y, 0.f);
                v.z = fmaxf(v.z, 0.f); v.w = fmaxf(v.w, 0.f);
            }
            *(float4*)(C + (size_t)r * N + col0) = v;
        }
    }
}

// ---------------- edge scatter: agg[dst] += xw[src] * dinv[src] ----------------
// grid.x = E, block = C/4 threads, vectorized f32x4 reduction.
__global__ void scatter_k(const float* __restrict__ xw, const int* __restrict__ src,
                          const int* __restrict__ dst, const float* __restrict__ dinv,
                          float* __restrict__ agg, int C) {
    const int e = blockIdx.x;
    const int s = __ldg(&src[e]);
    const int d = __ldg(&dst[e]);
    const float di = __ldg(&dinv[s]);
    const int c4 = threadIdx.x * 4;
    float4 v = *(const float4*)(xw + (size_t)s * C + c4);
    v.x *= di; v.y *= di; v.z *= di; v.w *= di;
    float* p = agg + (size_t)d * C + c4;
    asm volatile("red.global.add.v4.f32 [%0], {%1,%2,%3,%4};"
                 :: "l"(p), "f"(v.x), "f"(v.y), "f"(v.z), "f"(v.w) : "memory");
}

// ---------------- finalize: out = dinv*agg + dinv^2*xw + b (+add)(+relu) ------
template<int RELU, int ADD>
__global__ void finalize_k(const float* __restrict__ agg, const float* __restrict__ xw,
                           const float* __restrict__ dinv, const float* __restrict__ bias,
                           const float* __restrict__ addbuf, float* __restrict__ out,
                           int n, int C) {
    int idx = blockIdx.x * blockDim.x + threadIdx.x;
    int total = n * C;
    if (idx >= total) return;
    int r = idx / C;
    int c = idx - r * C;
    float di = __ldg(&dinv[r]);
    float v = di * agg[idx] + di * di * xw[idx] + __ldg(&bias[c]);
    if (ADD) v += addbuf[idx];
    if (RELU) v = fmaxf(v, 0.f);
    out[idx] = v;
}

// ---------------- batchnorm ----------------
__global__ void bn_stats_k(const float* __restrict__ h, float* __restrict__ sum,
                           float* __restrict__ sumsq, int n, int C) {
    int ch = blockIdx.x * blockDim.x + threadIdx.x;  // blockDim=128, gridDim.x=C/128
    float s = 0.f, ss = 0.f;
    for (int r = blockIdx.y; r < n; r += gridDim.y) {
        float v = h[(size_t)r * C + ch];
        s += v; ss += v * v;
    }
    atomicAdd(&sum[ch], s);
    atomicAdd(&sumsq[ch], ss);
}
__global__ void bn_apply_k(float* __restrict__ h, const float* __restrict__ sum,
                           const float* __restrict__ sumsq, const float* __restrict__ gam,
                           const float* __restrict__ bet, int n, int C) {
    int idx = blockIdx.x * blockDim.x + threadIdx.x;
    int total = n * C;
    if (idx >= total) return;
    int c = idx % C;
    float invn = 1.0f / (float)n;
    float mean = __ldg(&sum[c]) * invn;
    float var = __ldg(&sumsq[c]) * invn - mean * mean;
    float sc = __ldg(&gam[c]) * rsqrtf(var + EPS);
    float sh = __ldg(&bet[c]) - mean * sc;
    h[idx] = fmaxf(h[idx] * sc + sh, 0.f);
}

// ---------------- pooling ----------------
__global__ void pool_acc_k(const float* __restrict__ h, const int* __restrict__ batch,
                           float* __restrict__ pooled, float* __restrict__ cnt,
                           int n, int C) {
    int idx = blockIdx.x * blockDim.x + threadIdx.x;
    int total = n * C;
    if (idx >= total) return;
    int r = idx >> 10;           // C == 1024 here
    int c = idx & 1023;
    int g = __ldg(&batch[r]);
    atomicAdd(&pooled[(size_t)g * C + c], h[idx]);
    if (c == 0) atomicAdd(&cnt[g], 1.0f);
}
__global__ void pool_div_k(float* __restrict__ pooled, const float* __restrict__ cnt,
                           int nG, int C) {
    int idx = blockIdx.x * blockDim.x + threadIdx.x;
    if (idx >= nG * C) return;
    int g = idx / C;
    pooled[idx] /= fmaxf(__ldg(&cnt[g]), 1.0f);
}

// ---------------- host-side helpers ----------------
static float* symaddr(const void* sym) {
    void* p = nullptr;
    cudaGetSymbolAddress(&p, sym);
    return (float*)p;
}

static void launch_gemm(const float* A, const float* B, const float* bias, float* C,
                        int M, int K, int N, int relu, int hasbias) {
    dim3 grid(N / BN, (M + BM - 1) / BM);
    if (hasbias) {
        if (relu) gemm_k<1, 1><<<grid, 256>>>(A, B, bias, C, M, K, N);
        else      gemm_k<0, 1><<<grid, 256>>>(A, B, bias, C, M, K, N);
    } else {
        gemm_k<0, 0><<<grid, 256>>>(A, B, nullptr, C, M, K, N);
    }
}

// GCN conv: out = dinv*(scatter(xw*dinv)) + dinv^2*xw + bias  (+add) (+relu)
static void gcn(const float* hin, int Cin, const float* w, const float* bias, int Cout,
                const float* addbuf, int relu, float* out,
                float* xw, float* agg, const float* dinv,
                const int* src, const int* dst, int n, int E) {
    launch_gemm(hin, w, nullptr, xw, n, Cin, Cout, 0, 0);
    cudaMemsetAsync(agg, 0, (size_t)n * Cout * sizeof(float), 0);
    scatter_k<<<E, Cout / 4>>>(xw, src, dst, dinv, agg, Cout);
    int total = n * Cout;
    int nb = (total + 255) / 256;
    if (addbuf)      finalize_k<0, 1><<<nb, 256>>>(agg, xw, dinv, bias, addbuf, out, n, Cout);
    else if (relu)   finalize_k<1, 0><<<nb, 256>>>(agg, xw, dinv, bias, nullptr, out, n, Cout);
    else             finalize_k<0, 0><<<nb, 256>>>(agg, xw, dinv, bias, nullptr, out, n, Cout);
}

static void bn_relu(float* h, const float* gam, const float* bet, int n, int C,
                    float* sum, float* sumsq) {
    cudaMemsetAsync(sum, 0, C * sizeof(float), 0);
    cudaMemsetAsync(sumsq, 0, C * sizeof(float), 0);
    dim3 grid(C / 128, 80);
    bn_stats_k<<<grid, 128>>>(h, sum, sumsq, n, C);
    int total = n * C;
    bn_apply_k<<<(total + 255) / 256, 256>>>(h, sum, sumsq, gam, bet, n, C);
}

extern "C" void kernel_launch(void* const* d_in, const int* in_sizes, int n_in,
                              void* d_out, int out_size) {
    const float* x     = (const float*)d_in[0];
    const int*   ei    = (const int*)d_in[1];
    const int*   batch = (const int*)d_in[2];
    const float* w0 = (const float*)d_in[3];
    const float* b0 = (const float*)d_in[4];
    // blk0: w1 b1 g1 be1 w2 b2 g2 be2 w3 b3 at 5..14 ; blk1 at 15..24
    const float* mw1 = (const float*)d_in[25];
    const float* mb1 = (const float*)d_in[26];
    const float* mw2 = (const float*)d_in[27];
    const float* mb2 = (const float*)d_in[28];

    const int F = 128;
    const int n = in_sizes[0] / F;          // 20000
    const int E = in_sizes[1] / 2;          // 320000
    const int* src = ei;
    const int* dst = ei + E;

    float* bufA = symaddr(g_bufA);
    float* bufB = symaddr(g_bufB);
    float* bufC = symaddr(g_bufC);
    float* xw   = symaddr(g_xw);
    float* agg  = symaddr(g_agg);
    float* deg  = symaddr(g_deg);
    float* dinv = symaddr(g_dinv);
    float* sum  = symaddr(g_sum);
    float* sumsq= symaddr(g_sumsq);
    float* pool = symaddr(g_pool);
    float* cnt  = symaddr(g_cnt);
    float* mlp  = symaddr(g_mlp);

    // ---- degrees ----
    deg_init_k<<<(n + 255) / 256, 256>>>(deg, n);
    deg_acc_k<<<(E + 255) / 256, 256>>>(dst, deg, E);
    dinv_k<<<(n + 255) / 256, 256>>>(deg, dinv, n);

    // ---- stem: h = relu(gcn(x, w0, b0)), 128 -> 256 ----
    gcn(x, F, w0, b0, 256, nullptr, 1, bufA, xw, agg, dinv, src, dst, n, E);

    // ---- residual blocks ----
    const int Cin_arr[2]  = {256, 512};
    const int Cmid_arr[2] = {384, 768};
    const int Cout_arr[2] = {512, 1024};
    for (int blk = 0; blk < 2; blk++) {
        int base = 5 + blk * 10;
        const float* w1  = (const float*)d_in[base + 0];
        const float* b1  = (const float*)d_in[base + 1];
        const float* g1  = (const float*)d_in[base + 2];
        const float* be1 = (const float*)d_in[base + 3];
        const float* w2  = (const float*)d_in[base + 4];
        const float* b2  = (const float*)d_in[base + 5];
        const float* g2  = (const float*)d_in[base + 6];
        const float* be2 = (const float*)d_in[base + 7];
        const float* w3  = (const float*)d_in[base + 8];
        const float* b3  = (const float*)d_in[base + 9];
        int Cin = Cin_arr[blk], Cmid = Cmid_arr[blk], Cout = Cout_arr[blk];

        // t = relu(bn(gcn(h, w1, b1)))
        gcn(bufA, Cin, w1, b1, Cmid, nullptr, 0, bufB, xw, agg, dinv, src, dst, n, E);
        bn_relu(bufB, g1, be1, n, Cmid, sum, sumsq);
        // u = relu(bn(gcn(t, w2, b2)))
        gcn(bufB, Cmid, w2, b2, Cout, nullptr, 0, bufC, xw, agg, dinv, src, dst, n, E);
        bn_relu(bufC, g2, be2, n, Cout, sum, sumsq);
        // h = u + gcn(h, w3, b3)   (relu(u) == u since u >= 0)
        gcn(bufA, Cin, w3, b3, Cout, bufC, 0, bufA, xw, agg, dinv, src, dst, n, E);
    }

    // ---- global mean pool over graphs (C = 1024) ----
    const int C = 1024;
    cudaMemsetAsync(pool, 0, (size_t)NGRAPH * C * sizeof(float), 0);
    cudaMemsetAsync(cnt, 0, NGRAPH * sizeof(float), 0);
    pool_acc_k<<<((n * C) + 255) / 256, 256>>>(bufA, batch, pool, cnt, n, C);
    pool_div_k<<<((NGRAPH * C) + 255) / 256, 256>>>(pool, cnt, NGRAPH, C);

    // ---- MLP: relu(pool @ mw1 + mb1) @ mw2 + mb2 ----
    launch_gemm(pool, mw1, mb1, mlp, NGRAPH, 1024, 1024, 1, 1);
    launch_gemm(mlp, mw2, mb2, (float*)d_out, NGRAPH, 1024, 768, 0, 1);
}

// round 2
// speedup vs baseline: 1.4729x; 1.4729x over previous
#include <cuda_runtime.h>
#include <cuda_bf16.h>
#include <cstdint>

// ---------------- problem constants ----------------
#define MAXN 20000
#define MAXC 1024
#define NGRAPH 256
#define EPS 1e-5f

// ---------------- scratch (static device memory; no allocs) ----------------
__device__ float g_bufA[(size_t)MAXN * MAXC];  // h
__device__ float g_bufB[(size_t)MAXN * MAXC];  // t
__device__ float g_bufC[(size_t)MAXN * MAXC];  // u
__device__ float g_xw  [(size_t)MAXN * MAXC];
__device__ float g_agg [(size_t)MAXN * MAXC];
__device__ float g_deg [MAXN];
__device__ float g_dinv[MAXN];
__device__ float g_sum [MAXC];
__device__ float g_sumsq[MAXC];
__device__ float g_pool[NGRAPH * MAXC];
__device__ float g_cnt [NGRAPH];
__device__ float g_mlp [NGRAPH * MAXC];

// ---------------- degree / dinv ----------------
__global__ void deg_init_k(float* deg, int n) {
    int i = blockIdx.x * blockDim.x + threadIdx.x;
    if (i < n) deg[i] = 1.0f;
}
__global__ void deg_acc_k(const int* __restrict__ dst, float* deg, int E) {
    int i = blockIdx.x * blockDim.x + threadIdx.x;
    if (i < E) atomicAdd(&deg[dst[i]], 1.0f);
}
__global__ void dinv_k(const float* __restrict__ deg, float* dinv, int n) {
    int i = blockIdx.x * blockDim.x + threadIdx.x;
    if (i < n) dinv[i] = rsqrtf(deg[i]);
}

// =================== TF32 tensor-core GEMM =====================
// C[M,N] = A[M,K] @ B[K,N] (+bias)(+relu)
// CTA tile 128x128x16, 256 threads (8 warps, 4x2), warp tile 32x64.
// mma.sync.aligned.m16n8k8.row.col.f32.tf32.tf32.f32
#define TBM 128
#define TBN 128
#define TBK 16
#define ASTRIDE 20    // As[m][k]: 8 rows x 4 cols fragment reads conflict-free
#define BSTRIDE 136   // Bs[k][n]: 4 rows x 8 cols fragment reads conflict-free

__device__ __forceinline__ uint32_t f2tf32(float f) {
    uint32_t u;
    asm("cvt.rna.tf32.f32 %0, %1;" : "=r"(u) : "f"(f));
    return u;
}
__device__ __forceinline__ void mma_tf32(float* c, const uint32_t* a, const uint32_t* b) {
    asm volatile(
        "mma.sync.aligned.m16n8k8.row.col.f32.tf32.tf32.f32 "
        "{%0,%1,%2,%3}, {%4,%5,%6,%7}, {%8,%9}, {%0,%1,%2,%3};\n"
        : "+f"(c[0]), "+f"(c[1]), "+f"(c[2]), "+f"(c[3])
        : "r"(a[0]), "r"(a[1]), "r"(a[2]), "r"(a[3]), "r"(b[0]), "r"(b[1]));
}

template<int RELU, int BIAS>
__global__ __launch_bounds__(256)
void gemm_tf32_k(const float* __restrict__ A, const float* __restrict__ B,
                 const float* __restrict__ bias, float* __restrict__ C,
                 int M, int K, int N) {
    __shared__ __align__(16) uint32_t As[2][TBM][ASTRIDE];
    __shared__ __align__(16) uint32_t Bs[2][TBK][BSTRIDE];

    const int tid  = threadIdx.x;
    const int lane = tid & 31;
    const int wid  = tid >> 5;
    const int wm   = (wid & 3) * 32;    // warp row base
    const int wn   = (wid >> 2) * 64;   // warp col base
    const int bm0  = blockIdx.y * TBM;
    const int bn0  = blockIdx.x * TBN;

    // per-thread global-load coordinates
    const int a_row[2] = { (tid) >> 2, (tid + 256) >> 2 };           // 0..127
    const int a_c4 [2] = { (tid & 3) * 4, (tid & 3) * 4 };           // 0,4,8,12
    const int b_k  [2] = { tid >> 5, (tid + 256) >> 5 };             // 0..15
    const int b_n4 [2] = { (tid & 31) * 4, (tid & 31) * 4 };

    float acc[2][8][4];
#pragma unroll
    for (int i = 0; i < 2; i++)
#pragma unroll
        for (int j = 0; j < 8; j++)
#pragma unroll
            for (int l = 0; l < 4; l++) acc[i][j][l] = 0.f;

    const int ktiles = K / TBK;

    // ---- load tile 0 into buffer 0 ----
    {
#pragma unroll
        for (int l = 0; l < 2; l++) {
            int grow = bm0 + a_row[l];
            float4 av = make_float4(0.f, 0.f, 0.f, 0.f);
            if (grow < M) av = *(const float4*)(A + (size_t)grow * K + a_c4[l]);
            uint4 u = make_uint4(f2tf32(av.x), f2tf32(av.y), f2tf32(av.z), f2tf32(av.w));
            *(uint4*)&As[0][a_row[l]][a_c4[l]] = u;
            float4 bv = *(const float4*)(B + (size_t)b_k[l] * N + bn0 + b_n4[l]);
            uint4 w = make_uint4(f2tf32(bv.x), f2tf32(bv.y), f2tf32(bv.z), f2tf32(bv.w));
            *(uint4*)&Bs[0][b_k[l]][b_n4[l]] = w;
        }
    }
    __syncthreads();

    for (int kt = 0; kt < ktiles; kt++) {
        const int cur = kt & 1, nxt = cur ^ 1;
        const bool has = (kt + 1) < ktiles;
        float4 pa[2], pb[2];
        if (has) {
            const int koff = (kt + 1) * TBK;
#pragma unroll
            for (int l = 0; l < 2; l++) {
                int grow = bm0 + a_row[l];
                pa[l] = make_float4(0.f, 0.f, 0.f, 0.f);
                if (grow < M) pa[l] = *(const float4*)(A + (size_t)grow * K + koff + a_c4[l]);
                pb[l] = *(const float4*)(B + (size_t)(koff + b_k[l]) * N + bn0 + b_n4[l]);
            }
        }

        // ---- compute on cur ----
#pragma unroll
        for (int ks = 0; ks < 2; ks++) {
            const int k0 = ks * 8;
            uint32_t af[2][4], bf[8][2];
#pragma unroll
            for (int tm = 0; tm < 2; tm++) {
                int r0 = wm + tm * 16 + (lane >> 2);
                int c0 = k0 + (lane & 3);
                af[tm][0] = As[cur][r0][c0];
                af[tm][1] = As[cur][r0 + 8][c0];
                af[tm][2] = As[cur][r0][c0 + 4];
                af[tm][3] = As[cur][r0 + 8][c0 + 4];
            }
#pragma unroll
            for (int tn = 0; tn < 8; tn++) {
                int n0 = wn + tn * 8 + (lane >> 2);
                int r0 = k0 + (lane & 3);
                bf[tn][0] = Bs[cur][r0][n0];
                bf[tn][1] = Bs[cur][r0 + 4][n0];
            }
#pragma unroll
            for (int tm = 0; tm < 2; tm++)
#pragma unroll
                for (int tn = 0; tn < 8; tn++)
                    mma_tf32(acc[tm][tn], af[tm], bf[tn]);
        }

        if (has) {
#pragma unroll
            for (int l = 0; l < 2; l++) {
                uint4 u = make_uint4(f2tf32(pa[l].x), f2tf32(pa[l].y), f2tf32(pa[l].z), f2tf32(pa[l].w));
                *(uint4*)&As[nxt][a_row[l]][a_c4[l]] = u;
                uint4 w = make_uint4(f2tf32(pb[l].x), f2tf32(pb[l].y), f2tf32(pb[l].z), f2tf32(pb[l].w));
                *(uint4*)&Bs[nxt][b_k[l]][b_n4[l]] = w;
            }
        }
        __syncthreads();
    }

    // ---- epilogue ----
#pragma unroll
    for (int tm = 0; tm < 2; tm++) {
#pragma unroll
        for (int tn = 0; tn < 8; tn++) {
            int row = bm0 + wm + tm * 16 + (lane >> 2);
            int col = bn0 + wn + tn * 8 + (lane & 3) * 2;
            float b0 = 0.f, b1 = 0.f;
            if (BIAS) { b0 = __ldg(bias + col); b1 = __ldg(bias + col + 1); }
            float v0 = acc[tm][tn][0] + b0, v1 = acc[tm][tn][1] + b1;
            float v2 = acc[tm][tn][2] + b0, v3 = acc[tm][tn][3] + b1;
            if (RELU) {
                v0 = fmaxf(v0, 0.f); v1 = fmaxf(v1, 0.f);
                v2 = fmaxf(v2, 0.f); v3 = fmaxf(v3, 0.f);
            }
            if (row < M)     *(float2*)(C + (size_t)row * N + col)       = make_float2(v0, v1);
            if (row + 8 < M) *(float2*)(C + (size_t)(row + 8) * N + col) = make_float2(v2, v3);
        }
    }
}

// ---------------- fp32 tiled SIMT GEMM (small M; used for MLP) ----------------
#define BM 64
#define BN 64
#define BK 16
template<int RELU, int BIAS>
__global__ void gemm_k(const float* __restrict__ A, const float* __restrict__ B,
                       const float* __restrict__ bias, float* __restrict__ C,
                       int M, int K, int N) {
    __shared__ float As2[BK][BM];
    __shared__ float Bs2[BK][BN];
    const int tid = threadIdx.x;
    const int bcol = blockIdx.x, brow = blockIdx.y;
    const int tx = tid & 15, ty = tid >> 4;

    const int arow  = tid >> 2;
    const int acol4 = (tid & 3) * 4;
    const int brow_l = tid >> 4;
    const int bcol4  = (tid & 15) * 4;
    const int grow = brow * BM + arow;

    float acc[4][4];
#pragma unroll
    for (int i = 0; i < 4; i++)
#pragma unroll
        for (int j = 0; j < 4; j++) acc[i][j] = 0.f;

    for (int k0 = 0; k0 < K; k0 += BK) {
        float4 av = make_float4(0.f, 0.f, 0.f, 0.f);
        if (grow < M)
            av = *(const float4*)(A + (size_t)grow * K + k0 + acol4);
        As2[acol4 + 0][arow] = av.x;
        As2[acol4 + 1][arow] = av.y;
        As2[acol4 + 2][arow] = av.z;
        As2[acol4 + 3][arow] = av.w;
        float4 bv = *(const float4*)(B + (size_t)(k0 + brow_l) * N + bcol * BN + bcol4);
        *(float4*)(&Bs2[brow_l][bcol4]) = bv;
        __syncthreads();
#pragma unroll
        for (int k = 0; k < BK; k++) {
            float4 a = *(const float4*)(&As2[k][ty * 4]);
            float4 b = *(const float4*)(&Bs2[k][tx * 4]);
            float ar[4] = {a.x, a.y, a.z, a.w};
            float br[4] = {b.x, b.y, b.z, b.w};
#pragma unroll
            for (int i = 0; i < 4; i++)
#pragma unroll
                for (int j = 0; j < 4; j++)
                    acc[i][j] += ar[i] * br[j];
        }
        __syncthreads();
    }

    const int row0 = brow * BM + ty * 4;
    const int col0 = bcol * BN + tx * 4;
    float4 bb = make_float4(0.f, 0.f, 0.f, 0.f);
    if (BIAS) bb = *(const float4*)(bias + col0);
#pragma unroll
    for (int i = 0; i < 4; i++) {
        int r = row0 + i;
        if (r < M) {
            float4 v;
            v.x = acc[i][0]; v.y = acc[i][1]; v.z = acc[i][2]; v.w = acc[i][3];
            if (BIAS) { v.x += bb.x; v.y += bb.y; v.z += bb.z; v.w += bb.w; }
            if (RELU) {
                v.x = fmaxf(v.x, 0.f); v.y = fmaxf(v.y, 0.f);
                v.z = fmaxf(v.z, 0.f); v.w = fmaxf(v.w, 0.f);
            }
            *(float4*)(C + (size_t)r * N + col0) = v;
        }
    }
}

// ---------------- edge scatter: agg[dst] += xw[src] * dinv[src] ----------------
__global__ void scatter_k(const float* __restrict__ xw, const int* __restrict__ src,
                          const int* __restrict__ dst, const float* __restrict__ dinv,
                          float* __restrict__ agg, int C) {
    const int e = blockIdx.x;
    const int s = __ldg(&src[e]);
    const int d = __ldg(&dst[e]);
    const float di = __ldg(&dinv[s]);
    const int c4 = threadIdx.x * 4;
    float4 v = *(const float4*)(xw + (size_t)s * C + c4);
    v.x *= di; v.y *= di; v.z *= di; v.w *= di;
    float* p = agg + (size_t)d * C + c4;
    asm volatile("red.global.add.v4.f32 [%0], {%1,%2,%3,%4};"
                 :: "l"(p), "f"(v.x), "f"(v.y), "f"(v.z), "f"(v.w) : "memory");
}

// ---------------- finalize: out = dinv*agg + dinv^2*xw + b (+add)(+relu) ------
template<int RELU, int ADD>
__global__ void finalize_k(const float* __restrict__ agg, const float* __restrict__ xw,
                           const float* __restrict__ dinv, const float* __restrict__ bias,
                           const float* __restrict__ addbuf, float* __restrict__ out,
                           int n, int C) {
    int idx = blockIdx.x * blockDim.x + threadIdx.x;
    int total = n * C;
    if (idx >= total) return;
    int r = idx / C;
    int c = idx - r * C;
    float di = __ldg(&dinv[r]);
    float v = di * agg[idx] + di * di * xw[idx] + __ldg(&bias[c]);
    if (ADD) v += addbuf[idx];
    if (RELU) v = fmaxf(v, 0.f);
    out[idx] = v;
}

// ---------------- batchnorm ----------------
__global__ void bn_stats_k(const float* __restrict__ h, float* __restrict__ sum,
                           float* __restrict__ sumsq, int n, int C) {
    int ch = blockIdx.x * blockDim.x + threadIdx.x;
    float s = 0.f, ss = 0.f;
    for (int r = blockIdx.y; r < n; r += gridDim.y) {
        float v = h[(size_t)r * C + ch];
        s += v; ss += v * v;
    }
    atomicAdd(&sum[ch], s);
    atomicAdd(&sumsq[ch], ss);
}
__global__ void bn_apply_k(float* __restrict__ h, const float* __restrict__ sum,
                           const float* __restrict__ sumsq, const float* __restrict__ gam,
                           const float* __restrict__ bet, int n, int C) {
    int idx = blockIdx.x * blockDim.x + threadIdx.x;
    int total = n * C;
    if (idx >= total) return;
    int c = idx % C;
    float invn = 1.0f / (float)n;
    float mean = __ldg(&sum[c]) * invn;
    float var = __ldg(&sumsq[c]) * invn - mean * mean;
    float sc = __ldg(&gam[c]) * rsqrtf(var + EPS);
    float sh = __ldg(&bet[c]) - mean * sc;
    h[idx] = fmaxf(h[idx] * sc + sh, 0.f);
}

// ---------------- pooling ----------------
__global__ void pool_acc_k(const float* __restrict__ h, const int* __restrict__ batch,
                           float* __restrict__ pooled, float* __restrict__ cnt,
                           int n, int C) {
    int idx = blockIdx.x * blockDim.x + threadIdx.x;
    int total = n * C;
    if (idx >= total) return;
    int r = idx >> 10;
    int c = idx & 1023;
    int g = __ldg(&batch[r]);
    atomicAdd(&pooled[(size_t)g * C + c], h[idx]);
    if (c == 0) atomicAdd(&cnt[g], 1.0f);
}
__global__ void pool_div_k(float* __restrict__ pooled, const float* __restrict__ cnt,
                           int nG, int C) {
    int idx = blockIdx.x * blockDim.x + threadIdx.x;
    if (idx >= nG * C) return;
    int g = idx / C;
    pooled[idx] /= fmaxf(__ldg(&cnt[g]), 1.0f);
}

// ---------------- host-side helpers ----------------
static float* symaddr(const void* sym) {
    void* p = nullptr;
    cudaGetSymbolAddress(&p, sym);
    return (float*)p;
}

// big GEMM via tensor cores (N multiple of 128)
static void launch_gemm_big(const float* A, const float* B, float* C, int M, int K, int N) {
    dim3 grid(N / TBN, (M + TBM - 1) / TBM);
    gemm_tf32_k<0, 0><<<grid, 256>>>(A, B, nullptr, C, M, K, N);
}

static void launch_gemm_small(const float* A, const float* B, const float* bias, float* C,
                              int M, int K, int N, int relu) {
    dim3 grid(N / BN, (M + BM - 1) / BM);
    if (relu) gemm_k<1, 1><<<grid, 256>>>(A, B, bias, C, M, K, N);
    else      gemm_k<0, 1><<<grid, 256>>>(A, B, bias, C, M, K, N);
}

// GCN conv: out = dinv*(scatter(xw*dinv)) + dinv^2*xw + bias  (+add) (+relu)
static void gcn(const float* hin, int Cin, const float* w, const float* bias, int Cout,
                const float* addbuf, int relu, float* out,
                float* xw, float* agg, const float* dinv,
                const int* src, const int* dst, int n, int E) {
    launch_gemm_big(hin, w, xw, n, Cin, Cout);
    cudaMemsetAsync(agg, 0, (size_t)n * Cout * sizeof(float), 0);
    scatter_k<<<E, Cout / 4>>>(xw, src, dst, dinv, agg, Cout);
    int total = n * Cout;
    int nb = (total + 255) / 256;
    if (addbuf)      finalize_k<0, 1><<<nb, 256>>>(agg, xw, dinv, bias, addbuf, out, n, Cout);
    else if (relu)   finalize_k<1, 0><<<nb, 256>>>(agg, xw, dinv, bias, nullptr, out, n, Cout);
    else             finalize_k<0, 0><<<nb, 256>>>(agg, xw, dinv, bias, nullptr, out, n, Cout);
}

static void bn_relu(float* h, const float* gam, const float* bet, int n, int C,
                    float* sum, float* sumsq) {
    cudaMemsetAsync(sum, 0, C * sizeof(float), 0);
    cudaMemsetAsync(sumsq, 0, C * sizeof(float), 0);
    dim3 grid(C / 128, 80);
    bn_stats_k<<<grid, 128>>>(h, sum, sumsq, n, C);
    int total = n * C;
    bn_apply_k<<<(total + 255) / 256, 256>>>(h, sum, sumsq, gam, bet, n, C);
}

extern "C" void kernel_launch(void* const* d_in, const int* in_sizes, int n_in,
                              void* d_out, int out_size) {
    const float* x     = (const float*)d_in[0];
    const int*   ei    = (const int*)d_in[1];
    const int*   batch = (const int*)d_in[2];
    const float* w0 = (const float*)d_in[3];
    const float* b0 = (const float*)d_in[4];
    const float* mw1 = (const float*)d_in[25];
    const float* mb1 = (const float*)d_in[26];
    const float* mw2 = (const float*)d_in[27];
    const float* mb2 = (const float*)d_in[28];

    const int F = 128;
    const int n = in_sizes[0] / F;          // 20000
    const int E = in_sizes[1] / 2;          // 320000
    const int* src = ei;
    const int* dst = ei + E;

    float* bufA = symaddr(g_bufA);
    float* bufB = symaddr(g_bufB);
    float* bufC = symaddr(g_bufC);
    float* xw   = symaddr(g_xw);
    float* agg  = symaddr(g_agg);
    float* deg  = symaddr(g_deg);
    float* dinv = symaddr(g_dinv);
    float* sum  = symaddr(g_sum);
    float* sumsq= symaddr(g_sumsq);
    float* pool = symaddr(g_pool);
    float* cnt  = symaddr(g_cnt);
    float* mlp  = symaddr(g_mlp);

    // ---- degrees ----
    deg_init_k<<<(n + 255) / 256, 256>>>(deg, n);
    deg_acc_k<<<(E + 255) / 256, 256>>>(dst, deg, E);
    dinv_k<<<(n + 255) / 256, 256>>>(deg, dinv, n);

    // ---- stem: h = relu(gcn(x, w0, b0)), 128 -> 256 ----
    gcn(x, F, w0, b0, 256, nullptr, 1, bufA, xw, agg, dinv, src, dst, n, E);

    // ---- residual blocks ----
    const int Cin_arr[2]  = {256, 512};
    const int Cmid_arr[2] = {384, 768};
    const int Cout_arr[2] = {512, 1024};
    for (int blk = 0; blk < 2; blk++) {
        int base = 5 + blk * 10;
        const float* w1  = (const float*)d_in[base + 0];
        const float* b1  = (const float*)d_in[base + 1];
        const float* g1  = (const float*)d_in[base + 2];
        const float* be1 = (const float*)d_in[base + 3];
        const float* w2  = (const float*)d_in[base + 4];
        const float* b2  = (const float*)d_in[base + 5];
        const float* g2  = (const float*)d_in[base + 6];
        const float* be2 = (const float*)d_in[base + 7];
        const float* w3  = (const float*)d_in[base + 8];
        const float* b3  = (const float*)d_in[base + 9];
        int Cin = Cin_arr[blk], Cmid = Cmid_arr[blk], Cout = Cout_arr[blk];

        gcn(bufA, Cin, w1, b1, Cmid, nullptr, 0, bufB, xw, agg, dinv, src, dst, n, E);
        bn_relu(bufB, g1, be1, n, Cmid, sum, sumsq);
        gcn(bufB, Cmid, w2, b2, Cout, nullptr, 0, bufC, xw, agg, dinv, src, dst, n, E);
        bn_relu(bufC, g2, be2, n, Cout, sum, sumsq);
        gcn(bufA, Cin, w3, b3, Cout, bufC, 0, bufA, xw, agg, dinv, src, dst, n, E);
    }

    // ---- global mean pool over graphs (C = 1024) ----
    const int C = 1024;
    cudaMemsetAsync(pool, 0, (size_t)NGRAPH * C * sizeof(float), 0);
    cudaMemsetAsync(cnt, 0, NGRAPH * sizeof(float), 0);
    pool_acc_k<<<((n * C) + 255) / 256, 256>>>(bufA, batch, pool, cnt, n, C);
    pool_div_k<<<((NGRAPH * C) + 255) / 256, 256>>>(pool, cnt, NGRAPH, C);

    // ---- MLP: relu(pool @ mw1 + mb1) @ mw2 + mb2 ----
    launch_gemm_small(pool, mw1, mb1, mlp, NGRAPH, 1024, 1024, 1);
    launch_gemm_small(mlp, mw2, mb2, (float*)d_out, NGRAPH, 1024, 768, 0);
}

// round 3
// speedup vs baseline: 2.8972x; 1.9671x over previous
#include <cuda_runtime.h>
#include <cstdint>

// ---------------- problem constants ----------------
#define MAXN 20000
#define MAXE 512000
#define MAXC 1024
#define NGRAPH 256
#define EPS 1e-5f

// ---------------- scratch (static device memory; no allocs) ----------------
__device__ float g_bufA[(size_t)MAXN * MAXC];
__device__ float g_bufB[(size_t)MAXN * MAXC];
__device__ float g_bufC[(size_t)MAXN * MAXC];
__device__ float g_xws [(size_t)MAXN * MAXC];
__device__ float g_dinv[MAXN];
__device__ float g_sum [MAXC];
__device__ float g_sumsq[MAXC];
__device__ float g_pool[NGRAPH * MAXC];
__device__ float g_cnt [NGRAPH];
__device__ float g_mlp [NGRAPH * MAXC];
__device__ int   g_cnt_i[MAXN];
__device__ int   g_rowstart[MAXN + 1];
__device__ int   g_cursor[MAXN];
__device__ int   g_csr[MAXE];

// ---------------- graph preprocessing ----------------
__global__ void cnt_k(const int* __restrict__ dst, int* __restrict__ cnt, int E) {
    int i = blockIdx.x * blockDim.x + threadIdx.x;
    if (i < E) atomicAdd(&cnt[dst[i]], 1);
}
__global__ void dinv_k(const int* __restrict__ cnt, float* __restrict__ dinv, int n) {
    int i = blockIdx.x * blockDim.x + threadIdx.x;
    if (i < n) dinv[i] = rsqrtf(1.0f + (float)cnt[i]);
}
// single-block exclusive prefix scan over node counts
__global__ void prefix_k(const int* __restrict__ cnt, int* __restrict__ rowstart,
                         int* __restrict__ cursor, int n) {
    __shared__ int part[1024];
    const int t = threadIdx.x;
    const int per = (n + 1023) / 1024;
    const int base = t * per;
    int s = 0;
    for (int i = 0; i < per; i++) {
        int idx = base + i;
        if (idx < n) s += cnt[idx];
    }
    part[t] = s;
    __syncthreads();
    for (int off = 1; off < 1024; off <<= 1) {
        int v = (t >= off) ? part[t - off] : 0;
        __syncthreads();
        part[t] += v;
        __syncthreads();
    }
    int excl = (t == 0) ? 0 : part[t - 1];
    int run = excl;
    for (int i = 0; i < per; i++) {
        int idx = base + i;
        if (idx < n) {
            rowstart[idx] = run;
            cursor[idx] = run;
            run += cnt[idx];
        }
    }
    if (t == 1023) rowstart[n] = excl + s;
}
__global__ void fill_k(const int* __restrict__ src, const int* __restrict__ dst,
                       int* __restrict__ cursor, int* __restrict__ csr, int E) {
    int e = blockIdx.x * blockDim.x + threadIdx.x;
    if (e < E) {
        int pos = atomicAdd(&cursor[dst[e]], 1);
        csr[pos] = src[e];
    }
}

// =================== TF32 tensor-core GEMM (cp.async pipeline) =================
// C[M,N] = A[M,K] @ B[K,N], optional epilogue row-scale by dinv[row].
// fp32 bits fed directly to mma.tf32 (HW truncates mantissa).
#define TBM 128
#define TBN 128
#define TBK 16
#define STAGES 4
#define ASTRIDE 20
#define BSTRIDE 136
#define A_TILE (TBM * ASTRIDE)              // 2560 floats
#define B_TILE (TBK * BSTRIDE)              // 2176 floats
#define STAGE_FLOATS (A_TILE + B_TILE)      // 4736
#define GEMM_SMEM (STAGES * STAGE_FLOATS * 4)

__device__ __forceinline__ void cp_async16(uint32_t saddr, const void* gaddr, int srcsize) {
    asm volatile("cp.async.cg.shared.global [%0], [%1], 16, %2;"
                 :: "r"(saddr), "l"(gaddr), "r"(srcsize));
}
__device__ __forceinline__ void mma_tf32(float* c, const uint32_t* a, const uint32_t* b) {
    asm volatile(
        "mma.sync.aligned.m16n8k8.row.col.f32.tf32.tf32.f32 "
        "{%0,%1,%2,%3}, {%4,%5,%6,%7}, {%8,%9}, {%0,%1,%2,%3};\n"
        : "+f"(c[0]), "+f"(c[1]), "+f"(c[2]), "+f"(c[3])
        : "r"(a[0]), "r"(a[1]), "r"(a[2]), "r"(a[3]), "r"(b[0]), "r"(b[1]));
}

__device__ __forceinline__ void load_tile(float* stage, const float* A, const float* B,
                                          int M, int K, int N, int bm0, int bn0, int k0,
                                          int tid) {
    float* sa = stage;
    float* sb = stage + A_TILE;
#pragma unroll
    for (int l = 0; l < 2; l++) {
        int idx = tid + l * 256;
        // A: 128 rows x 16 cols
        int arow = idx >> 2, ac4 = (idx & 3) * 4;
        const float* ga = A + (size_t)(bm0 + arow) * K + k0 + ac4;
        uint32_t da = (uint32_t)__cvta_generic_to_shared(sa + arow * ASTRIDE + ac4);
        cp_async16(da, ga, (bm0 + arow) < M ? 16 : 0);
        // B: 16 rows x 128 cols
        int bk = idx >> 5, bn4 = (idx & 31) * 4;
        const float* gb = B + (size_t)(k0 + bk) * N + bn0 + bn4;
        uint32_t db = (uint32_t)__cvta_generic_to_shared(sb + bk * BSTRIDE + bn4);
        cp_async16(db, gb, 16);
    }
}

template<int SCALE>
__global__ __launch_bounds__(256, 2)
void gemm_tf32_k(const float* __restrict__ A, const float* __restrict__ B,
                 const float* __restrict__ dinv, float* __restrict__ C,
                 int M, int K, int N) {
    extern __shared__ float sm[];
    const int tid  = threadIdx.x;
    const int lane = tid & 31;
    const int wid  = tid >> 5;
    const int wm   = (wid & 3) * 32;
    const int wn   = (wid >> 2) * 64;
    const int bm0  = blockIdx.y * TBM;
    const int bn0  = blockIdx.x * TBN;

    float acc[2][8][4];
#pragma unroll
    for (int i = 0; i < 2; i++)
#pragma unroll
        for (int j = 0; j < 8; j++)
#pragma unroll
            for (int l = 0; l < 4; l++) acc[i][j][l] = 0.f;

    const int ktiles = K / TBK;

    // prologue: fill STAGES-1 stages
#pragma unroll
    for (int s = 0; s < STAGES - 1; s++) {
        load_tile(sm + s * STAGE_FLOATS, A, B, M, K, N, bm0, bn0, s * TBK, tid);
        asm volatile("cp.async.commit_group;");
    }

    for (int kt = 0; kt < ktiles; kt++) {
        asm volatile("cp.async.wait_group %0;" :: "n"(STAGES - 2));
        __syncthreads();
        const float* sa = sm + (kt % STAGES) * STAGE_FLOATS;
        const float* sb = sa + A_TILE;

#pragma unroll
        for (int ks = 0; ks < 2; ks++) {
            const int k0 = ks * 8;
            uint32_t af[2][4], bf[8][2];
#pragma unroll
            for (int tm = 0; tm < 2; tm++) {
                int r0 = wm + tm * 16 + (lane >> 2);
                int c0 = k0 + (lane & 3);
                af[tm][0] = __float_as_uint(sa[r0 * ASTRIDE + c0]);
                af[tm][1] = __float_as_uint(sa[(r0 + 8) * ASTRIDE + c0]);
                af[tm][2] = __float_as_uint(sa[r0 * ASTRIDE + c0 + 4]);
                af[tm][3] = __float_as_uint(sa[(r0 + 8) * ASTRIDE + c0 + 4]);
            }
#pragma unroll
            for (int tn = 0; tn < 8; tn++) {
                int n0 = wn + tn * 8 + (lane >> 2);
                int r0 = k0 + (lane & 3);
                bf[tn][0] = __float_as_uint(sb[r0 * BSTRIDE + n0]);
                bf[tn][1] = __float_as_uint(sb[(r0 + 4) * BSTRIDE + n0]);
            }
#pragma unroll
            for (int tm = 0; tm < 2; tm++)
#pragma unroll
                for (int tn = 0; tn < 8; tn++)
                    mma_tf32(acc[tm][tn], af[tm], bf[tn]);
        }

        int nk = kt + STAGES - 1;
        if (nk < ktiles)
            load_tile(sm + (nk % STAGES) * STAGE_FLOATS, A, B, M, K, N, bm0, bn0, nk * TBK, tid);
        asm volatile("cp.async.commit_group;");
        __syncthreads();
    }

    // epilogue
#pragma unroll
    for (int tm = 0; tm < 2; tm++) {
        int row = bm0 + wm + tm * 16 + (lane >> 2);
        float d0 = 1.f, d8 = 1.f;
        if (SCALE) {
            d0 = (row < M) ? __ldg(dinv + row) : 0.f;
            d8 = (row + 8 < M) ? __ldg(dinv + row + 8) : 0.f;
        }
#pragma unroll
        for (int tn = 0; tn < 8; tn++) {
            int col = bn0 + wn + tn * 8 + (lane & 3) * 2;
            float v0 = acc[tm][tn][0] * d0, v1 = acc[tm][tn][1] * d0;
            float v2 = acc[tm][tn][2] * d8, v3 = acc[tm][tn][3] * d8;
            if (row < M)     *(float2*)(C + (size_t)row * N + col)       = make_float2(v0, v1);
            if (row + 8 < M) *(float2*)(C + (size_t)(row + 8) * N + col) = make_float2(v2, v3);
        }
    }
}

// ---------------- fused gather-aggregate + finalize ----------------
// out[r] = dinv[r] * (xws[r] + sum_{s in in(r)} xws[s]) (+bias)(+add)(+relu)
template<int RELU, int ADD, int BIAS>
__global__ void aggregate_k(const float* __restrict__ xws, const int* __restrict__ csr,
                            const int* __restrict__ rowstart, const float* __restrict__ dinv,
                            const float* __restrict__ bias, const float* __restrict__ addbuf,
                            float* __restrict__ out, int C4) {
    const int r = blockIdx.x;
    const int t = threadIdx.x;
    const float4* base = (const float4*)xws;
    float4 acc = base[(size_t)r * C4 + t];  // self term (pre-scaled by dinv[r])
    int j   = __ldg(&rowstart[r]);
    int end = __ldg(&rowstart[r + 1]);
    for (; j + 2 <= end; j += 2) {
        int s0 = __ldg(&csr[j]);
        int s1 = __ldg(&csr[j + 1]);
        float4 v0 = base[(size_t)s0 * C4 + t];
        float4 v1 = base[(size_t)s1 * C4 + t];
        acc.x += v0.x + v1.x; acc.y += v0.y + v1.y;
        acc.z += v0.z + v1.z; acc.w += v0.w + v1.w;
    }
    if (j < end) {
        int s0 = __ldg(&csr[j]);
        float4 v0 = base[(size_t)s0 * C4 + t];
        acc.x += v0.x; acc.y += v0.y; acc.z += v0.z; acc.w += v0.w;
    }
    const float di = __ldg(&dinv[r]);
    float4 o = make_float4(acc.x * di, acc.y * di, acc.z * di, acc.w * di);
    if (BIAS) {
        float4 b = *(const float4*)(bias + t * 4);
        o.x += b.x; o.y += b.y; o.z += b.z; o.w += b.w;
    }
    if (ADD) {
        float4 a = ((const float4*)addbuf)[(size_t)r * C4 + t];
        o.x += a.x; o.y += a.y; o.z += a.z; o.w += a.w;
    }
    if (RELU) {
        o.x = fmaxf(o.x, 0.f); o.y = fmaxf(o.y, 0.f);
        o.z = fmaxf(o.z, 0.f); o.w = fmaxf(o.w, 0.f);
    }
    ((float4*)out)[(size_t)r * C4 + t] = o;
}

// ---------------- fp32 tiled SIMT GEMM (small M; MLP) ----------------
#define BM 64
#define BN 64
#define BK 16
template<int RELU>
__global__ void gemm_k(const float* __restrict__ A, const float* __restrict__ B,
                       const float* __restrict__ bias, float* __restrict__ C,
                       int M, int K, int N) {
    __shared__ float As2[BK][BM];
    __shared__ float Bs2[BK][BN];
    const int tid = threadIdx.x;
    const int bcol = blockIdx.x, brow = blockIdx.y;
    const int tx = tid & 15, ty = tid >> 4;

    const int arow  = tid >> 2;
    const int acol4 = (tid & 3) * 4;
    const int brow_l = tid >> 4;
    const int bcol4  = (tid & 15) * 4;
    const int grow = brow * BM + arow;

    float acc[4][4];
#pragma unroll
    for (int i = 0; i < 4; i++)
#pragma unroll
        for (int j = 0; j < 4; j++) acc[i][j] = 0.f;

    for (int k0 = 0; k0 < K; k0 += BK) {
        float4 av = make_float4(0.f, 0.f, 0.f, 0.f);
        if (grow < M)
            av = *(const float4*)(A + (size_t)grow * K + k0 + acol4);
        As2[acol4 + 0][arow] = av.x;
        As2[acol4 + 1][arow] = av.y;
        As2[acol4 + 2][arow] = av.z;
        As2[acol4 + 3][arow] = av.w;
        float4 bv = *(const float4*)(B + (size_t)(k0 + brow_l) * N + bcol * BN + bcol4);
        *(float4*)(&Bs2[brow_l][bcol4]) = bv;
        __syncthreads();
#pragma unroll
        for (int k = 0; k < BK; k++) {
            float4 a = *(const float4*)(&As2[k][ty * 4]);
            float4 b = *(const float4*)(&Bs2[k][tx * 4]);
            float ar[4] = {a.x, a.y, a.z, a.w};
            float br[4] = {b.x, b.y, b.z, b.w};
#pragma unroll
            for (int i = 0; i < 4; i++)
#pragma unroll
                for (int j = 0; j < 4; j++)
                    acc[i][j] += ar[i] * br[j];
        }
        __syncthreads();
    }

    const int row0 = brow * BM + ty * 4;
    const int col0 = bcol * BN + tx * 4;
    float4 bb = *(const float4*)(bias + col0);
#pragma unroll
    for (int i = 0; i < 4; i++) {
        int r = row0 + i;
        if (r < M) {
            float4 v;
            v.x = acc[i][0] + bb.x; v.y = acc[i][1] + bb.y;
            v.z = acc[i][2] + bb.z; v.w = acc[i][3] + bb.w;
            if (RELU) {
                v.x = fmaxf(v.x, 0.f); v.y = fmaxf(v.y, 0.f);
                v.z = fmaxf(v.z, 0.f); v.w = fmaxf(v.w, 0.f);
            }
            *(float4*)(C + (size_t)r * N + col0) = v;
        }
    }
}

// ---------------- batchnorm ----------------
__global__ void bn_stats_k(const float* __restrict__ h, float* __restrict__ sum,
                           float* __restrict__ sumsq, int n, int C) {
    int ch = blockIdx.x * blockDim.x + threadIdx.x;
    float s = 0.f, ss = 0.f;
    for (int r = blockIdx.y; r < n; r += gridDim.y) {
        float v = h[(size_t)r * C + ch];
        s += v; ss += v * v;
    }
    atomicAdd(&sum[ch], s);
    atomicAdd(&sumsq[ch], ss);
}
__global__ void bn_apply_k(float* __restrict__ h, const float* __restrict__ sum,
                           const float* __restrict__ sumsq, const float* __restrict__ gam,
                           const float* __restrict__ bet, int n, int C) {
    int idx = blockIdx.x * blockDim.x + threadIdx.x;
    int total = n * C;
    if (idx >= total) return;
    int c = idx % C;
    float invn = 1.0f / (float)n;
    float mean = __ldg(&sum[c]) * invn;
    float var = __ldg(&sumsq[c]) * invn - mean * mean;
    float sc = __ldg(&gam[c]) * rsqrtf(var + EPS);
    float sh = __ldg(&bet[c]) - mean * sc;
    h[idx] = fmaxf(h[idx] * sc + sh, 0.f);
}

// ---------------- pooling ----------------
__global__ void pool_acc_k(const float* __restrict__ h, const int* __restrict__ batch,
                           float* __restrict__ pooled, float* __restrict__ cnt,
                           int n, int C) {
    int idx = blockIdx.x * blockDim.x + threadIdx.x;
    int total = n * C;
    if (idx >= total) return;
    int r = idx >> 10;
    int c = idx & 1023;
    int g = __ldg(&batch[r]);
    atomicAdd(&pooled[(size_t)g * C + c], h[idx]);
    if (c == 0) atomicAdd(&cnt[g], 1.0f);
}
__global__ void pool_div_k(float* __restrict__ pooled, const float* __restrict__ cnt,
                           int nG, int C) {
    int idx = blockIdx.x * blockDim.x + threadIdx.x;
    if (idx >= nG * C) return;
    int g = idx / C;
    pooled[idx] /= fmaxf(__ldg(&cnt[g]), 1.0f);
}

// ---------------- host-side helpers ----------------
static float* symaddrf(const void* sym) {
    void* p = nullptr;
    cudaGetSymbolAddress(&p, sym);
    return (float*)p;
}
static int* symaddri(const void* sym) {
    void* p = nullptr;
    cudaGetSymbolAddress(&p, sym);
    return (int*)p;
}

static void launch_gemm_xws(const float* A, const float* B, const float* dinv, float* C,
                            int M, int K, int N) {
    dim3 grid(N / TBN, (M + TBM - 1) / TBM);
    gemm_tf32_k<1><<<grid, 256, GEMM_SMEM>>>(A, B, dinv, C, M, K, N);
}

// GCN conv via CSR: xws = (h @ w) * dinv[row]; out = aggregate(+bias)(+add)(+relu)
static void gcn(const float* hin, int Cin, const float* w, const float* bias, int Cout,
                const float* addbuf, int relu, float* out,
                float* xws, const float* dinv, const int* csr, const int* rowstart, int n) {
    launch_gemm_xws(hin, w, dinv, xws, n, Cin, Cout);
    int C4 = Cout / 4;
    if (addbuf)
        aggregate_k<0, 1, 1><<<n, C4>>>(xws, csr, rowstart, dinv, bias, addbuf, out, C4);
    else if (relu)
        aggregate_k<1, 0, 1><<<n, C4>>>(xws, csr, rowstart, dinv, bias, nullptr, out, C4);
    else
        aggregate_k<0, 0, 0><<<n, C4>>>(xws, csr, rowstart, dinv, nullptr, nullptr, out, C4);
}

static void bn_relu(float* h, const float* gam, const float* bet, int n, int C,
                    float* sum, float* sumsq) {
    cudaMemsetAsync(sum, 0, C * sizeof(float), 0);
    cudaMemsetAsync(sumsq, 0, C * sizeof(float), 0);
    dim3 grid(C / 128, 80);
    bn_stats_k<<<grid, 128>>>(h, sum, sumsq, n, C);
    int total = n * C;
    bn_apply_k<<<(total + 255) / 256, 256>>>(h, sum, sumsq, gam, bet, n, C);
}

extern "C" void kernel_launch(void* const* d_in, const int* in_sizes, int n_in,
                              void* d_out, int out_size) {
    const float* x     = (const float*)d_in[0];
    const int*   ei    = (const int*)d_in[1];
    const int*   batch = (const int*)d_in[2];
    const float* w0 = (const float*)d_in[3];
    const float* b0 = (const float*)d_in[4];
    const float* mw1 = (const float*)d_in[25];
    const float* mb1 = (const float*)d_in[26];
    const float* mw2 = (const float*)d_in[27];
    const float* mb2 = (const float*)d_in[28];

    const int F = 128;
    const int n = in_sizes[0] / F;          // 20000
    const int E = in_sizes[1] / 2;          // 320000
    const int* src = ei;
    const int* dst = ei + E;

    float* bufA = symaddrf(g_bufA);
    float* bufB = symaddrf(g_bufB);
    float* bufC = symaddrf(g_bufC);
    float* xws  = symaddrf(g_xws);
    float* dinv = symaddrf(g_dinv);
    float* sum  = symaddrf(g_sum);
    float* sumsq= symaddrf(g_sumsq);
    float* pool = symaddrf(g_pool);
    float* cnt  = symaddrf(g_cnt);
    float* mlp  = symaddrf(g_mlp);
    int* cnt_i    = symaddri(g_cnt_i);
    int* rowstart = symaddri(g_rowstart);
    int* cursor   = symaddri(g_cursor);
    int* csr      = symaddri(g_csr);

    // raise dynamic smem limit for the tf32 GEMM (host-side attr, not a stream op)
    static int attr_done = 0;
    if (!attr_done) {
        cudaFuncSetAttribute(gemm_tf32_k<1>, cudaFuncAttributeMaxDynamicSharedMemorySize, GEMM_SMEM);
        cudaFuncSetAttribute(gemm_tf32_k<0>, cudaFuncAttributeMaxDynamicSharedMemorySize, GEMM_SMEM);
        attr_done = 1;
    }

    // ---- CSR build + dinv ----
    cudaMemsetAsync(cnt_i, 0, n * sizeof(int), 0);
    cnt_k<<<(E + 255) / 256, 256>>>(dst, cnt_i, E);
    dinv_k<<<(n + 255) / 256, 256>>>(cnt_i, dinv, n);
    prefix_k<<<1, 1024>>>(cnt_i, rowstart, cursor, n);
    fill_k<<<(E + 255) / 256, 256>>>(src, dst, cursor, csr, E);

    // ---- stem: h = relu(gcn(x, w0, b0)), 128 -> 256 ----
    gcn(x, F, w0, b0, 256, nullptr, 1, bufA, xws, dinv, csr, rowstart, n);

    // ---- residual blocks ----
    const int Cin_arr[2]  = {256, 512};
    const int Cmid_arr[2] = {384, 768};
    const int Cout_arr[2] = {512, 1024};
    for (int blk = 0; blk < 2; blk++) {
        int base = 5 + blk * 10;
        const float* w1  = (const float*)d_in[base + 0];
        const float* g1  = (const float*)d_in[base + 2];
        const float* be1 = (const float*)d_in[base + 3];
        const float* w2  = (const float*)d_in[base + 4];
        const float* g2  = (const float*)d_in[base + 6];
        const float* be2 = (const float*)d_in[base + 7];
        const float* w3  = (const float*)d_in[base + 8];
        const float* b3  = (const float*)d_in[base + 9];
        int Cin = Cin_arr[blk], Cmid = Cmid_arr[blk], Cout = Cout_arr[blk];

        // t = relu(bn(gcn(h, w1))) — conv bias cancels inside BN, skip it
        gcn(bufA, Cin, w1, nullptr, Cmid, nullptr, 0, bufB, xws, dinv, csr, rowstart, n);
        bn_relu(bufB, g1, be1, n, Cmid, sum, sumsq);
        // u = relu(bn(gcn(t, w2)))
        gcn(bufB, Cmid, w2, nullptr, Cout, nullptr, 0, bufC, xws, dinv, csr, rowstart, n);
        bn_relu(bufC, g2, be2, n, Cout, sum, sumsq);
        // h = u + gcn(h, w3, b3)
        gcn(bufA, Cin, w3, b3, Cout, bufC, 0, bufA, xws, dinv, csr, rowstart, n);
    }

    // ---- global mean pool over graphs (C = 1024) ----
    const int C = 1024;
    cudaMemsetAsync(pool, 0, (size_t)NGRAPH * C * sizeof(float), 0);
    cudaMemsetAsync(cnt, 0, NGRAPH * sizeof(float), 0);
    pool_acc_k<<<((n * C) + 255) / 256, 256>>>(bufA, batch, pool, cnt, n, C);
    pool_div_k<<<((NGRAPH * C) + 255) / 256, 256>>>(pool, cnt, NGRAPH, C);

    // ---- MLP: relu(pool @ mw1 + mb1) @ mw2 + mb2 ----
    {
        dim3 g1(1024 / BN, (NGRAPH + BM - 1) / BM);
        gemm_k<1><<<g1, 256>>>(pool, mw1, mb1, mlp, NGRAPH, 1024, 1024);
        dim3 g2(768 / BN, (NGRAPH + BM - 1) / BM);
        gemm_k<0><<<g2, 256>>>(mlp, mw2, mb2, (float*)d_out, NGRAPH, 1024, 768);
    }
}